// round 3
// baseline (speedup 1.0000x reference)
#include <cuda_runtime.h>
#include <cuda_bf16.h>
#include <cstdint>
#include <cstddef>

#define HH 1024
#define TT 256
#define BB 64
#define BT (BB*TT)       /* 16384 */
#define G4 (4*HH)        /* 4096 */
#define NBLK_REC 128

/* lstm1 (128x128) pipeline constants */
#define ASTRIDE 20
#define STAGE_ELEMS (128*ASTRIDE)   /* 2560 floats per tile stage */

/* big gemm (128x256) pipeline constants */
#define GSTR 20
#define G_AT (128*GSTR)             /* 2560 */
#define G_ST ((128+256)*GSTR)       /* 7680 floats per stage */

/* recurrence */
#define RC_CH  16      /* chunks per step  */
#define RC_CK  64      /* K per chunk      */
#define RC_PAD 68      /* padded row floats */
#define RC_BUFE (64*RC_PAD)
#define RC_NBUF 4

// ------------------------- scratch (device globals; no cudaMalloc allowed) ---
__device__ __align__(256) float g_gates[(size_t)BT * G4];   // 256 MB xg scratch
__device__ __align__(256) float g_h1[(size_t)BT * HH];      // 64 MB
__device__ __align__(256) float g_h2[(size_t)BT * HH];      // 64 MB
__device__ __align__(256) float g_hbuf[2 * BB * HH];
__device__ __align__(256) float g_z1[BB * HH];
__device__ __align__(256) float g_z2[BB * (HH/2)];
__device__ volatile unsigned g_cnt = 0;
__device__ volatile unsigned g_sense = 0;

// ------------------------- helpers ------------------------------------------
__device__ __forceinline__ float tf32r(float x) {
    uint32_t u;
    asm("cvt.rna.tf32.f32 %0, %1;" : "=r"(u) : "f"(x));
    return __uint_as_float(u);
}
__device__ __forceinline__ uint32_t fbits(float x) { return __float_as_uint(x); }

__device__ __forceinline__ void mma_tf32(float c[4],
                                         uint32_t a0, uint32_t a1, uint32_t a2, uint32_t a3,
                                         uint32_t b0, uint32_t b1) {
    asm volatile(
        "mma.sync.aligned.m16n8k8.row.col.f32.tf32.tf32.f32 "
        "{%0,%1,%2,%3}, {%4,%5,%6,%7}, {%8,%9}, {%0,%1,%2,%3};"
        : "+f"(c[0]), "+f"(c[1]), "+f"(c[2]), "+f"(c[3])
        : "r"(a0), "r"(a1), "r"(a2), "r"(a3), "r"(b0), "r"(b1));
}

__device__ __forceinline__ float sigf(float x) { return 1.0f / (1.0f + expf(-x)); }

__device__ __forceinline__ void cp16(uint32_t dsh, const void* src) {
    asm volatile("cp.async.cg.shared.global [%0], [%1], 16;" :: "r"(dsh), "l"(src));
}
__device__ __forceinline__ void cp_commit() { asm volatile("cp.async.commit_group;"); }

// =============================================================================
// BIG GEMM: C = A @ W^T (+bias, +ReLU).  BM=128, BN=256, BK=16, 3-stage
// cp.async. 8 warps as 2(M) x 4(N); warp tile 64x64. 1 CTA/SM.
// =============================================================================
template<int RELU>
__launch_bounds__(256, 1)
__global__ void gemm_kernel(const float* __restrict__ A, long long asr,
                            const float* __restrict__ W,
                            const float* __restrict__ b1p, const float* __restrict__ b2p,
                            float* __restrict__ C, int M, int N, int K)
{
    extern __shared__ float sm[];

    const int tid = threadIdx.x, lane = tid & 31, warp = tid >> 5;
    const int wm = warp >> 2, wn = warp & 3;
    const int mb = blockIdx.y * 128, nb = blockIdx.x * 256;

    float acc[4][8][4];
#pragma unroll
    for (int a = 0; a < 4; a++)
#pragma unroll
        for (int b = 0; b < 8; b++)
#pragma unroll
            for (int c = 0; c < 4; c++) acc[a][b][c] = 0.0f;

    // staging maps
    const int aslot0 = tid;                 // + 256 for second
    const int bslot0 = tid;                 // +256, +512, +768
    const uint32_t smbase = (uint32_t)__cvta_generic_to_shared(sm);

    const float* aptr[2];
    uint32_t     adst[2];
#pragma unroll
    for (int i = 0; i < 2; i++) {
        const int slot = aslot0 + i * 256;
        int row = slot >> 2;
        const int kc = (slot & 3) * 4;
        int gr = mb + row; if (gr > M - 1) gr = M - 1;
        aptr[i] = A + (size_t)gr * asr + kc;
        adst[i] = smbase + (uint32_t)((row * GSTR + kc) * 4);
    }
    const float* bptr[4];
    uint32_t     bdst[4];
#pragma unroll
    for (int i = 0; i < 4; i++) {
        const int slot = bslot0 + i * 256;
        const int row = slot >> 2;
        const int kc = (slot & 3) * 4;
        bptr[i] = W + (size_t)(nb + row) * K + kc;
        bdst[i] = smbase + (uint32_t)((G_AT + row * GSTR + kc) * 4);
    }

    const int KT = K >> 4;

    auto issue = [&](int kt) {
        const uint32_t so = (uint32_t)((kt % 3) * G_ST * 4);
        const int koff = kt * 16;
#pragma unroll
        for (int i = 0; i < 2; i++) cp16(adst[i] + so, aptr[i] + koff);
#pragma unroll
        for (int i = 0; i < 4; i++) cp16(bdst[i] + so, bptr[i] + koff);
        cp_commit();
    };

    issue(0); if (KT > 1) issue(1);

    for (int kt = 0; kt < KT; ++kt) {
        if (kt < KT - 1) asm volatile("cp.async.wait_group 1;");
        else             asm volatile("cp.async.wait_group 0;");
        __syncthreads();
        if (kt + 2 < KT) issue(kt + 2);

        const float* Ab = sm + (kt % 3) * G_ST;
        const float* Bb = Ab + G_AT;
#pragma unroll
        for (int kk = 0; kk < 16; kk += 8) {
            uint32_t af[4][4], bfr[8][2];
#pragma unroll
            for (int mt = 0; mt < 4; mt++) {
                const int r = wm * 64 + mt * 16 + (lane >> 2);
                const int c = kk + (lane & 3);
                af[mt][0] = fbits(Ab[r * GSTR + c]);
                af[mt][1] = fbits(Ab[(r + 8) * GSTR + c]);
                af[mt][2] = fbits(Ab[r * GSTR + c + 4]);
                af[mt][3] = fbits(Ab[(r + 8) * GSTR + c + 4]);
            }
#pragma unroll
            for (int nt = 0; nt < 8; nt++) {
                const int n = wn * 64 + nt * 8 + (lane >> 2);
                bfr[nt][0] = fbits(Bb[n * GSTR + kk + (lane & 3)]);
                bfr[nt][1] = fbits(Bb[n * GSTR + kk + (lane & 3) + 4]);
            }
#pragma unroll
            for (int mt = 0; mt < 4; mt++)
#pragma unroll
                for (int nt = 0; nt < 8; nt++)
                    mma_tf32(acc[mt][nt], af[mt][0], af[mt][1], af[mt][2], af[mt][3],
                             bfr[nt][0], bfr[nt][1]);
        }
    }

    // epilogue
#pragma unroll
    for (int mt = 0; mt < 4; mt++) {
#pragma unroll
        for (int nt = 0; nt < 8; nt++) {
            const int row0 = mb + wm * 64 + mt * 16 + (lane >> 2);
            const int col  = nb + wn * 64 + nt * 8 + 2 * (lane & 3);
            const float b0v = (b1p ? b1p[col]     : 0.f) + (b2p ? b2p[col]     : 0.f);
            const float b1v = (b1p ? b1p[col + 1] : 0.f) + (b2p ? b2p[col + 1] : 0.f);
            float v0 = acc[mt][nt][0] + b0v, v1 = acc[mt][nt][1] + b1v;
            float v2 = acc[mt][nt][2] + b0v, v3 = acc[mt][nt][3] + b1v;
            if (RELU) {
                v0 = fmaxf(v0, 0.f); v1 = fmaxf(v1, 0.f);
                v2 = fmaxf(v2, 0.f); v3 = fmaxf(v3, 0.f);
            }
            if (row0 < M)     *(float2*)(C + (size_t)row0 * N + col)       = make_float2(v0, v1);
            if (row0 + 8 < M) *(float2*)(C + (size_t)(row0 + 8) * N + col) = make_float2(v2, v3);
        }
    }
}

// =============================================================================
// lstm1 helper: 128x128 tile accumulate, 4-stage cp.async (R2 design)
// =============================================================================
__device__ __forceinline__ void run_gemm_acc(
    const float* __restrict__ A, long long asr, int M, int mb,
    const float* __restrict__ Wslab, int K,
    float* As, float* Bs, float (&acc)[4][4][4])
{
    const int tid  = threadIdx.x;
    const int lane = tid & 31, warp = tid >> 5;
    const int wm = warp >> 2, wn = warp & 3;
    const int lrow = tid >> 2;
    const int lkc  = (tid & 3) * 4;

    int r0 = mb + lrow;      if (r0 > M - 1) r0 = M - 1;
    int r1 = mb + lrow + 64; if (r1 > M - 1) r1 = M - 1;
    const float* a0p = A + (size_t)r0 * asr + lkc;
    const float* a1p = A + (size_t)r1 * asr + lkc;
    const float* b0p = Wslab + (size_t)lrow * K + lkc;
    const float* b1p = Wslab + (size_t)(lrow + 64) * K + lkc;

    const uint32_t sA  = (uint32_t)__cvta_generic_to_shared(As) + (uint32_t)((lrow * ASTRIDE + lkc) * 4);
    const uint32_t sA2 = sA + 64 * ASTRIDE * 4;
    const uint32_t sB  = (uint32_t)__cvta_generic_to_shared(Bs) + (uint32_t)((lrow * ASTRIDE + lkc) * 4);
    const uint32_t sB2 = sB + 64 * ASTRIDE * 4;

    const int KT = K >> 4;

    auto issue = [&](int kt) {
        const int koff = kt * 16;
        const uint32_t so = (uint32_t)((kt & 3) * STAGE_ELEMS * 4);
        cp16(sA  + so, a0p + koff);
        cp16(sA2 + so, a1p + koff);
        cp16(sB  + so, b0p + koff);
        cp16(sB2 + so, b1p + koff);
        cp_commit();
    };

    const int pre = KT < 3 ? KT : 3;
    for (int s = 0; s < pre; ++s) issue(s);

    for (int kt = 0; kt < KT; ++kt) {
        if (kt < KT - 2)       asm volatile("cp.async.wait_group 2;");
        else if (kt == KT - 2) asm volatile("cp.async.wait_group 1;");
        else                   asm volatile("cp.async.wait_group 0;");
        __syncthreads();
        if (kt + 3 < KT) issue(kt + 3);

        const float* Ab = As + (kt & 3) * STAGE_ELEMS;
        const float* Bb = Bs + (kt & 3) * STAGE_ELEMS;
#pragma unroll
        for (int kk = 0; kk < 16; kk += 8) {
            uint32_t af[4][4], bfr[4][2];
#pragma unroll
            for (int mt = 0; mt < 4; mt++) {
                const int r = wm * 64 + mt * 16 + (lane >> 2);
                const int c = kk + (lane & 3);
                af[mt][0] = fbits(Ab[r * ASTRIDE + c]);
                af[mt][1] = fbits(Ab[(r + 8) * ASTRIDE + c]);
                af[mt][2] = fbits(Ab[r * ASTRIDE + c + 4]);
                af[mt][3] = fbits(Ab[(r + 8) * ASTRIDE + c + 4]);
            }
#pragma unroll
            for (int nt = 0; nt < 4; nt++) {
                const int n = wn * 32 + nt * 8 + (lane >> 2);
                bfr[nt][0] = fbits(Bb[n * ASTRIDE + kk + (lane & 3)]);
                bfr[nt][1] = fbits(Bb[n * ASTRIDE + kk + (lane & 3) + 4]);
            }
#pragma unroll
            for (int mt = 0; mt < 4; mt++)
#pragma unroll
                for (int nt = 0; nt < 4; nt++)
                    mma_tf32(acc[mt][nt], af[mt][0], af[mt][1], af[mt][2], af[mt][3],
                             bfr[nt][0], bfr[nt][1]);
        }
    }
    __syncthreads();
}

// ------------------------- fused lstm1 step ----------------------------------
__launch_bounds__(256, 1)
__global__ void lstm1_kernel(const float* __restrict__ A, long long asr,
                             const float* __restrict__ W,
                             const float* __restrict__ bih, const float* __restrict__ bhh,
                             float* __restrict__ Hout, int M, int K)
{
    extern __shared__ float sm[];
    float* As = sm;
    float* Bs = sm + 4 * STAGE_ELEMS;

    const int tid = threadIdx.x, lane = tid & 31, warp = tid >> 5;
    const int wm = warp >> 2, wn = warp & 3;
    const int mb = blockIdx.y * 128, nb = blockIdx.x * 128;

    float keep[4][4][4];
    const int gset[3] = {0, 2, 3};   // i, g, o

#pragma unroll 1
    for (int ph = 0; ph < 3; ++ph) {
        const int g = gset[ph];
        float acc[4][4][4];
#pragma unroll
        for (int a = 0; a < 4; a++)
#pragma unroll
            for (int b = 0; b < 4; b++)
#pragma unroll
                for (int c = 0; c < 4; c++) acc[a][b][c] = 0.0f;

        run_gemm_acc(A, asr, M, mb, W + ((size_t)(g * HH + nb)) * K, K, As, Bs, acc);

#pragma unroll
        for (int mt = 0; mt < 4; mt++) {
#pragma unroll
            for (int nt = 0; nt < 4; nt++) {
                const int gcol = g * HH + nb + wn * 32 + nt * 8 + 2 * (lane & 3);
                const float b0 = bih[gcol] + bhh[gcol];
                const float b1 = bih[gcol + 1] + bhh[gcol + 1];
                if (ph == 0) {
                    keep[mt][nt][0] = sigf(acc[mt][nt][0] + b0);
                    keep[mt][nt][1] = sigf(acc[mt][nt][1] + b1);
                    keep[mt][nt][2] = sigf(acc[mt][nt][2] + b0);
                    keep[mt][nt][3] = sigf(acc[mt][nt][3] + b1);
                } else if (ph == 1) {
                    keep[mt][nt][0] *= tanhf(acc[mt][nt][0] + b0);
                    keep[mt][nt][1] *= tanhf(acc[mt][nt][1] + b1);
                    keep[mt][nt][2] *= tanhf(acc[mt][nt][2] + b0);
                    keep[mt][nt][3] *= tanhf(acc[mt][nt][3] + b1);
                } else {
                    const int row0 = mb + wm * 64 + mt * 16 + (lane >> 2);
                    const int colh = nb + wn * 32 + nt * 8 + 2 * (lane & 3);
                    const float v0 = sigf(acc[mt][nt][0] + b0) * tanhf(keep[mt][nt][0]);
                    const float v1 = sigf(acc[mt][nt][1] + b1) * tanhf(keep[mt][nt][1]);
                    const float v2 = sigf(acc[mt][nt][2] + b0) * tanhf(keep[mt][nt][2]);
                    const float v3 = sigf(acc[mt][nt][3] + b1) * tanhf(keep[mt][nt][3]);
                    *(float2*)(Hout + (size_t)row0 * HH + colh)       = make_float2(v0, v1);
                    *(float2*)(Hout + (size_t)(row0 + 8) * HH + colh) = make_float2(v2, v3);
                }
            }
        }
    }
}

// ------------------------- grid barrier --------------------------------------
__device__ __forceinline__ void grid_bar()
{
    __threadfence();
    __syncthreads();
    if (threadIdx.x == 0) {
        const unsigned gen = g_sense;
        const unsigned arrived = atomicAdd((unsigned*)&g_cnt, 1u);
        if (arrived == NBLK_REC - 1u) {
            g_cnt = 0;
            __threadfence();
            atomicAdd((unsigned*)&g_sense, 1u);
        } else {
            while (g_sense == gen) { __nanosleep(32); }
        }
        __threadfence();
    }
    __syncthreads();
}

// ------------------------- recurrent LSTM layer ------------------------------
// 4-slot, depth-3 cp.async chunk pipeline; c in registers; 1 barrier/step.
__launch_bounds__(256, 1)
__global__ void recur_kernel(const float* __restrict__ xg,   // [BT, 4096]
                             const float* __restrict__ Whh,  // [4096, 1024]
                             float* __restrict__ hs,         // [BT, 1024]
                             float* __restrict__ hbuf,       // [2, 64, 1024]
                             int write_all)
{
    extern __shared__ float sm[];
    float* Ws = sm;                       // [32][1028]
    float* hS = sm + 32 * 1028;           // RC_NBUF * RC_BUFE
    float* gS = hS;                       // overlay on slot 0 (safe post-loop)

    const int tid = threadIdx.x, lane = tid & 31, warp = tid >> 5;
    const int wm = warp >> 1, wn = warp & 1;     // 4(M) x 2(N)
    const int n0 = blockIdx.x * 8;

#pragma unroll 1
    for (int c = 0; c < 32; c++) {
        const int g = c >> 3, j = c & 7;
        const float4 v = *(const float4*)(Whh + ((size_t)(g * HH + n0 + j)) * HH + tid * 4);
        float* d = Ws + c * 1028 + tid * 4;
        d[0] = tf32r(v.x); d[1] = tf32r(v.y); d[2] = tf32r(v.z); d[3] = tf32r(v.w);
    }
    __syncthreads();

    const int arow = wm * 16 + (lane >> 2);
    const int kofs = lane & 3;
    const int r0 = tid >> 3, j0 = tid & 7, r1 = 32 + (tid >> 3);
    float c0 = 0.f, c1 = 0.f;

    const uint32_t hS_sh = (uint32_t)__cvta_generic_to_shared(hS);

    for (int t = 0; t < TT; t++) {
        const size_t x0 = ((size_t)(r0 * TT + t)) * G4 + n0 + j0;
        const size_t x1 = ((size_t)(r1 * TT + t)) * G4 + n0 + j0;
        const float xi0 = xg[x0], xf0 = xg[x0 + 1024], xg0 = xg[x0 + 2048], xo0 = xg[x0 + 3072];
        const float xi1 = xg[x1], xf1 = xg[x1 + 1024], xg1 = xg[x1 + 2048], xo1 = xg[x1 + 3072];

        float acc[2][4] = {{0,0,0,0},{0,0,0,0}};

        if (t > 0) {
            const float* hsrc = hbuf + (size_t)(t & 1) * (BB * HH);

            auto issue = [&](int ch) {
                const int slot = ch & 3;
#pragma unroll
                for (int i = 0; i < 4; i++) {
                    const int v = tid + i * 256;
                    const int r = v >> 4, kseg = v & 15;
                    const float4* src = (const float4*)hsrc + (size_t)r * 256 + ch * 16 + kseg;
                    const uint32_t dst = hS_sh + (uint32_t)((slot * RC_BUFE + r * RC_PAD + kseg * 4) * 4);
                    cp16(dst, src);
                }
                cp_commit();
            };

            issue(0); issue(1); issue(2);
#pragma unroll 1
            for (int ch = 0; ch < RC_CH; ++ch) {
                if (ch < RC_CH - 2)       asm volatile("cp.async.wait_group 2;");
                else if (ch == RC_CH - 2) asm volatile("cp.async.wait_group 1;");
                else                      asm volatile("cp.async.wait_group 0;");
                __syncthreads();
                if (ch + 3 < RC_CH) issue(ch + 3);

                const float* hb = hS + (ch & 3) * RC_BUFE;
#pragma unroll
                for (int ks = 0; ks < 8; ++ks) {
                    const int kk = ks * 8;
                    const uint32_t a0 = fbits(hb[arow * RC_PAD + kk + kofs]);
                    const uint32_t a1 = fbits(hb[(arow + 8) * RC_PAD + kk + kofs]);
                    const uint32_t a2 = fbits(hb[arow * RC_PAD + kk + kofs + 4]);
                    const uint32_t a3 = fbits(hb[(arow + 8) * RC_PAD + kk + kofs + 4]);
#pragma unroll
                    for (int nt = 0; nt < 2; nt++) {
                        const int ncol = wn * 16 + nt * 8 + (lane >> 2);
                        const int kg = ch * RC_CK + kk + kofs;
                        const uint32_t b0 = fbits(Ws[ncol * 1028 + kg]);
                        const uint32_t b1 = fbits(Ws[ncol * 1028 + kg + 4]);
                        mma_tf32(acc[nt], a0, a1, a2, a3, b0, b1);
                    }
                }
            }

            {
                const int rr = wm * 16 + (lane >> 2);
#pragma unroll
                for (int nt = 0; nt < 2; nt++) {
                    const int cc = wn * 16 + nt * 8 + 2 * (lane & 3);
                    gS[rr * 33 + cc]           = acc[nt][0];
                    gS[rr * 33 + cc + 1]       = acc[nt][1];
                    gS[(rr + 8) * 33 + cc]     = acc[nt][2];
                    gS[(rr + 8) * 33 + cc + 1] = acc[nt][3];
                }
            }
            __syncthreads();
        }

        float gi0 = xi0, gf0 = xf0, gg0 = xg0, go0 = xo0;
        float gi1 = xi1, gf1 = xf1, gg1 = xg1, go1 = xo1;
        if (t > 0) {
            gi0 += gS[r0 * 33 + j0];      gf0 += gS[r0 * 33 + 8 + j0];
            gg0 += gS[r0 * 33 + 16 + j0]; go0 += gS[r0 * 33 + 24 + j0];
            gi1 += gS[r1 * 33 + j0];      gf1 += gS[r1 * 33 + 8 + j0];
            gg1 += gS[r1 * 33 + 16 + j0]; go1 += gS[r1 * 33 + 24 + j0];
        }
        c0 = sigf(gf0) * c0 + sigf(gi0) * tanhf(gg0);
        c1 = sigf(gf1) * c1 + sigf(gi1) * tanhf(gg1);
        const float h0v = sigf(go0) * tanhf(c0);
        const float h1v = sigf(go1) * tanhf(c1);

        float* hdst = hbuf + (size_t)((t + 1) & 1) * (BB * HH);
        hdst[r0 * HH + n0 + j0] = h0v;
        hdst[r1 * HH + n0 + j0] = h1v;
        if (write_all || t == TT - 1) {
            hs[((size_t)(r0 * TT + t)) * HH + n0 + j0] = h0v;
            hs[((size_t)(r1 * TT + t)) * HH + n0 + j0] = h1v;
        }

        if (t < TT - 1) grid_bar();
    }
}

// ------------------------- final MLP layer 3 ---------------------------------
__global__ void mlp3_kernel(const float* __restrict__ z2, const float* __restrict__ W3,
                            const float* __restrict__ b3, float* __restrict__ out)
{
    __shared__ float red[8];
    const int b = blockIdx.x;
    float s = 0.f;
    for (int k = threadIdx.x; k < 512; k += 256) s += z2[b * 512 + k] * W3[k];
#pragma unroll
    for (int o = 16; o; o >>= 1) s += __shfl_down_sync(0xffffffffu, s, o);
    if ((threadIdx.x & 31) == 0) red[threadIdx.x >> 5] = s;
    __syncthreads();
    if (threadIdx.x < 8) {
        s = red[threadIdx.x];
#pragma unroll
        for (int o = 4; o; o >>= 1) s += __shfl_down_sync(0xffu, s, o);
        if (threadIdx.x == 0) out[b] = s + b3[0];
    }
}

// ------------------------- launcher ------------------------------------------
extern "C" void kernel_launch(void* const* d_in, const int* in_sizes, int n_in,
                              void* d_out, int out_size)
{
    const float* xx       = (const float*)d_in[0];
    const float* l1_Wih0  = (const float*)d_in[1];
    const float* l1_bih0  = (const float*)d_in[2];
    const float* l1_bhh0  = (const float*)d_in[3];
    const float* l1_Wih1  = (const float*)d_in[4];
    const float* l1_bih1  = (const float*)d_in[5];
    const float* l1_bhh1  = (const float*)d_in[6];
    const float* l2_Wih0  = (const float*)d_in[7];
    const float* l2_Whh0  = (const float*)d_in[8];
    const float* l2_bih0  = (const float*)d_in[9];
    const float* l2_bhh0  = (const float*)d_in[10];
    const float* l2_Wih1  = (const float*)d_in[11];
    const float* l2_Whh1  = (const float*)d_in[12];
    const float* l2_bih1  = (const float*)d_in[13];
    const float* l2_bhh1  = (const float*)d_in[14];
    const float* mlp_W1   = (const float*)d_in[15];
    const float* mlp_b1   = (const float*)d_in[16];
    const float* mlp_W2   = (const float*)d_in[17];
    const float* mlp_b2   = (const float*)d_in[18];
    const float* mlp_W3   = (const float*)d_in[19];
    const float* mlp_b3   = (const float*)d_in[20];
    float* out = (float*)d_out;

    void* p;
    cudaGetSymbolAddress(&p, g_gates); float* gates = (float*)p;
    cudaGetSymbolAddress(&p, g_h1);    float* h1    = (float*)p;
    cudaGetSymbolAddress(&p, g_h2);    float* h2    = (float*)p;
    cudaGetSymbolAddress(&p, g_hbuf);  float* hbuf  = (float*)p;
    cudaGetSymbolAddress(&p, g_z1);    float* z1    = (float*)p;
    cudaGetSymbolAddress(&p, g_z2);    float* z2    = (float*)p;

    const int lstm1_smem = 8 * STAGE_ELEMS * 4;                      // 81920 B
    const int gemm_smem  = 3 * G_ST * 4;                             // 92160 B
    const int recur_smem = (32 * 1028 + RC_NBUF * RC_BUFE) * 4;      // 201216 B
    cudaFuncSetAttribute(gemm_kernel<0>, cudaFuncAttributeMaxDynamicSharedMemorySize, gemm_smem);
    cudaFuncSetAttribute(gemm_kernel<1>, cudaFuncAttributeMaxDynamicSharedMemorySize, gemm_smem);
    cudaFuncSetAttribute(lstm1_kernel,   cudaFuncAttributeMaxDynamicSharedMemorySize, lstm1_smem);
    cudaFuncSetAttribute(recur_kernel,   cudaFuncAttributeMaxDynamicSharedMemorySize, recur_smem);

    const dim3 blk(256);

    // lstm1 (fused, f gate skipped)
    lstm1_kernel<<<dim3(HH / 128, BT / 128), blk, lstm1_smem>>>(xx, 256, l1_Wih0, l1_bih0, l1_bhh0, h1, BT, 256);
    lstm1_kernel<<<dim3(HH / 128, BT / 128), blk, lstm1_smem>>>(h1, HH, l1_Wih1, l1_bih1, l1_bhh1, h2, BT, HH);

    // lstm2 layer 0: xg GEMM split into 2 half-launches (so ncu -s 5 lands on
    // the full xg1 GEMM below), then recurrence
    gemm_kernel<0><<<dim3(G4 / 256, 64), blk, gemm_smem>>>(h2, HH, l2_Wih0, l2_bih0, l2_bhh0, gates, BT/2, G4, HH);
    gemm_kernel<0><<<dim3(G4 / 256, 64), blk, gemm_smem>>>(h2 + (size_t)(BT/2) * HH, HH, l2_Wih0, l2_bih0, l2_bhh0,
                                                           gates + (size_t)(BT/2) * G4, BT/2, G4, HH);
    recur_kernel<<<NBLK_REC, blk, recur_smem>>>(gates, l2_Whh0, h1, hbuf, 1);

    // lstm2 layer 1 (launch index 5 = this GEMM -> profiled by ncu)
    gemm_kernel<0><<<dim3(G4 / 256, BT / 128), blk, gemm_smem>>>(h1, HH, l2_Wih1, l2_bih1, l2_bhh1, gates, BT, G4, HH);
    recur_kernel<<<NBLK_REC, blk, recur_smem>>>(gates, l2_Whh1, h2, hbuf, 0);

    // MLP on last timestep
    gemm_kernel<1><<<dim3(HH / 256, 1), blk, gemm_smem>>>(h2 + (size_t)(TT - 1) * HH, (long long)TT * HH,
                                                          mlp_W1, mlp_b1, nullptr, z1, BB, HH, HH);
    gemm_kernel<1><<<dim3((HH / 2) / 256, 1), blk, gemm_smem>>>(z1, HH, mlp_W2, mlp_b2, nullptr,
                                                                z2, BB, HH / 2, HH);
    mlp3_kernel<<<BB, blk>>>(z2, mlp_W3, mlp_b3, out);
}

// round 4
// speedup vs baseline: 1.1938x; 1.1938x over previous
#include <cuda_runtime.h>
#include <cuda_bf16.h>
#include <cstdint>
#include <cstddef>

#define HH 1024
#define TT 256
#define BB 64
#define BT (BB*TT)       /* 16384 */
#define G4 (4*HH)        /* 4096 */
#define NBLK_REC 128

/* lstm1 (128x128) pipeline constants */
#define ASTRIDE 20
#define STAGE_ELEMS (128*ASTRIDE)

/* big gemm (128x256) pipeline constants */
#define GSTR 20
#define G_AT (128*GSTR)
#define G_ST ((128+256)*GSTR)

/* recurrence SMEM float offsets */
#define RW_FLOATS (32*1028)            /* 32896: weight slab           */
#define RT_BUF    8192                 /* floats per 32KB h chunk buf  */
#define RP_STR    34                   /* partial row stride           */
#define RP_SZ     (64*RP_STR)          /* 2176 floats per partial      */
#define R_MBAR_F  (RW_FLOATS + 8*RP_SZ)        /* 50304 */
#define R_SMEM_B  ((R_MBAR_F + 16) * 4)        /* 201280 bytes */

// ------------------------- scratch (device globals) --------------------------
__device__ __align__(256) float g_gates[(size_t)BT * G4];   // 256 MB xg scratch
__device__ __align__(256) float g_h1[(size_t)BT * HH];
__device__ __align__(256) float g_h2[(size_t)BT * HH];
__device__ __align__(256) float g_hbufT[2 * HH * BB];       // transposed, XOR-swizzled
__device__ __align__(256) float g_z1[BB * HH];
__device__ __align__(256) float g_z2[BB * (HH/2)];
__device__ volatile unsigned g_cnt = 0;
__device__ volatile unsigned g_sense = 0;

// ------------------------- helpers ------------------------------------------
__device__ __forceinline__ float tf32r(float x) {
    uint32_t u;
    asm("cvt.rna.tf32.f32 %0, %1;" : "=r"(u) : "f"(x));
    return __uint_as_float(u);
}
__device__ __forceinline__ uint32_t fbits(float x) { return __float_as_uint(x); }

__device__ __forceinline__ void mma_tf32(float c[4],
                                         uint32_t a0, uint32_t a1, uint32_t a2, uint32_t a3,
                                         uint32_t b0, uint32_t b1) {
    asm volatile(
        "mma.sync.aligned.m16n8k8.row.col.f32.tf32.tf32.f32 "
        "{%0,%1,%2,%3}, {%4,%5,%6,%7}, {%8,%9}, {%0,%1,%2,%3};"
        : "+f"(c[0]), "+f"(c[1]), "+f"(c[2]), "+f"(c[3])
        : "r"(a0), "r"(a1), "r"(a2), "r"(a3), "r"(b0), "r"(b1));
}

__device__ __forceinline__ float sigf(float x) { return 1.0f / (1.0f + expf(-x)); }

__device__ __forceinline__ void cp16(uint32_t dsh, const void* src) {
    asm volatile("cp.async.cg.shared.global [%0], [%1], 16;" :: "r"(dsh), "l"(src));
}
__device__ __forceinline__ void cp_commit() { asm volatile("cp.async.commit_group;"); }

__device__ __forceinline__ void mbar_init(uint32_t mbar, uint32_t cnt) {
    asm volatile("mbarrier.init.shared.b64 [%0], %1;" :: "r"(mbar), "r"(cnt) : "memory");
}
__device__ __forceinline__ void mbar_expect(uint32_t mbar, uint32_t bytes) {
    asm volatile("mbarrier.arrive.expect_tx.shared.b64 _, [%0], %1;" :: "r"(mbar), "r"(bytes) : "memory");
}
__device__ __forceinline__ void bulk_g2s(uint32_t dst, const void* src, uint32_t bytes, uint32_t mbar) {
    asm volatile("cp.async.bulk.shared::cluster.global.mbarrier::complete_tx::bytes [%0], [%1], %2, [%3];"
                 :: "r"(dst), "l"(src), "r"(bytes), "r"(mbar) : "memory");
}
__device__ __forceinline__ void mbar_wait(uint32_t mbar, uint32_t parity) {
    uint32_t done;
    asm volatile(
        "{\n\t.reg .pred p;\n\t"
        "mbarrier.try_wait.parity.acquire.cta.shared::cta.b64 p, [%1], %2;\n\t"
        "selp.b32 %0, 1, 0, p;\n\t}"
        : "=r"(done) : "r"(mbar), "r"(parity) : "memory");
    if (!done) {
        asm volatile(
            "{\n\t.reg .pred P1;\n\t"
            "WL_%=:\n\t"
            "mbarrier.try_wait.parity.acquire.cta.shared::cta.b64 P1, [%0], %1, 0x989680;\n\t"
            "@P1 bra.uni WD_%=;\n\t"
            "bra.uni WL_%=;\n\t"
            "WD_%=:\n\t}"
            :: "r"(mbar), "r"(parity) : "memory");
    }
}

// =============================================================================
// BIG GEMM (unchanged from R3): BM=128, BN=256, BK=16, 3-stage cp.async
// =============================================================================
template<int RELU>
__launch_bounds__(256, 1)
__global__ void gemm_kernel(const float* __restrict__ A, long long asr,
                            const float* __restrict__ W,
                            const float* __restrict__ b1p, const float* __restrict__ b2p,
                            float* __restrict__ C, int M, int N, int K)
{
    extern __shared__ float sm[];
    const int tid = threadIdx.x, lane = tid & 31, warp = tid >> 5;
    const int wm = warp >> 2, wn = warp & 3;
    const int mb = blockIdx.y * 128, nb = blockIdx.x * 256;

    float acc[4][8][4];
#pragma unroll
    for (int a = 0; a < 4; a++)
#pragma unroll
        for (int b = 0; b < 8; b++)
#pragma unroll
            for (int c = 0; c < 4; c++) acc[a][b][c] = 0.0f;

    const uint32_t smbase = (uint32_t)__cvta_generic_to_shared(sm);
    const float* aptr[2]; uint32_t adst[2];
#pragma unroll
    for (int i = 0; i < 2; i++) {
        const int slot = tid + i * 256;
        int row = slot >> 2;
        const int kc = (slot & 3) * 4;
        int gr = mb + row; if (gr > M - 1) gr = M - 1;
        aptr[i] = A + (size_t)gr * asr + kc;
        adst[i] = smbase + (uint32_t)((row * GSTR + kc) * 4);
    }
    const float* bptr[4]; uint32_t bdst[4];
#pragma unroll
    for (int i = 0; i < 4; i++) {
        const int slot = tid + i * 256;
        const int row = slot >> 2;
        const int kc = (slot & 3) * 4;
        bptr[i] = W + (size_t)(nb + row) * K + kc;
        bdst[i] = smbase + (uint32_t)((G_AT + row * GSTR + kc) * 4);
    }

    const int KT = K >> 4;
    auto issue = [&](int kt) {
        const uint32_t so = (uint32_t)((kt % 3) * G_ST * 4);
        const int koff = kt * 16;
#pragma unroll
        for (int i = 0; i < 2; i++) cp16(adst[i] + so, aptr[i] + koff);
#pragma unroll
        for (int i = 0; i < 4; i++) cp16(bdst[i] + so, bptr[i] + koff);
        cp_commit();
    };

    issue(0); if (KT > 1) issue(1);

    for (int kt = 0; kt < KT; ++kt) {
        if (kt < KT - 1) asm volatile("cp.async.wait_group 1;");
        else             asm volatile("cp.async.wait_group 0;");
        __syncthreads();
        if (kt + 2 < KT) issue(kt + 2);

        const float* Ab = sm + (kt % 3) * G_ST;
        const float* Bb = Ab + G_AT;
#pragma unroll
        for (int kk = 0; kk < 16; kk += 8) {
            uint32_t af[4][4], bfr[8][2];
#pragma unroll
            for (int mt = 0; mt < 4; mt++) {
                const int r = wm * 64 + mt * 16 + (lane >> 2);
                const int c = kk + (lane & 3);
                af[mt][0] = fbits(Ab[r * GSTR + c]);
                af[mt][1] = fbits(Ab[(r + 8) * GSTR + c]);
                af[mt][2] = fbits(Ab[r * GSTR + c + 4]);
                af[mt][3] = fbits(Ab[(r + 8) * GSTR + c + 4]);
            }
#pragma unroll
            for (int nt = 0; nt < 8; nt++) {
                const int n = wn * 64 + nt * 8 + (lane >> 2);
                bfr[nt][0] = fbits(Bb[n * GSTR + kk + (lane & 3)]);
                bfr[nt][1] = fbits(Bb[n * GSTR + kk + (lane & 3) + 4]);
            }
#pragma unroll
            for (int mt = 0; mt < 4; mt++)
#pragma unroll
                for (int nt = 0; nt < 8; nt++)
                    mma_tf32(acc[mt][nt], af[mt][0], af[mt][1], af[mt][2], af[mt][3],
                             bfr[nt][0], bfr[nt][1]);
        }
    }

#pragma unroll
    for (int mt = 0; mt < 4; mt++) {
#pragma unroll
        for (int nt = 0; nt < 8; nt++) {
            const int row0 = mb + wm * 64 + mt * 16 + (lane >> 2);
            const int col  = nb + wn * 64 + nt * 8 + 2 * (lane & 3);
            const float b0v = (b1p ? b1p[col]     : 0.f) + (b2p ? b2p[col]     : 0.f);
            const float b1v = (b1p ? b1p[col + 1] : 0.f) + (b2p ? b2p[col + 1] : 0.f);
            float v0 = acc[mt][nt][0] + b0v, v1 = acc[mt][nt][1] + b1v;
            float v2 = acc[mt][nt][2] + b0v, v3 = acc[mt][nt][3] + b1v;
            if (RELU) {
                v0 = fmaxf(v0, 0.f); v1 = fmaxf(v1, 0.f);
                v2 = fmaxf(v2, 0.f); v3 = fmaxf(v3, 0.f);
            }
            if (row0 < M)     *(float2*)(C + (size_t)row0 * N + col)       = make_float2(v0, v1);
            if (row0 + 8 < M) *(float2*)(C + (size_t)(row0 + 8) * N + col) = make_float2(v2, v3);
        }
    }
}

// =============================================================================
// lstm1 helper + kernel (unchanged from R3)
// =============================================================================
__device__ __forceinline__ void run_gemm_acc(
    const float* __restrict__ A, long long asr, int M, int mb,
    const float* __restrict__ Wslab, int K,
    float* As, float* Bs, float (&acc)[4][4][4])
{
    const int tid  = threadIdx.x;
    const int lane = tid & 31, warp = tid >> 5;
    const int wm = warp >> 2, wn = warp & 3;
    const int lrow = tid >> 2;
    const int lkc  = (tid & 3) * 4;

    int r0 = mb + lrow;      if (r0 > M - 1) r0 = M - 1;
    int r1 = mb + lrow + 64; if (r1 > M - 1) r1 = M - 1;
    const float* a0p = A + (size_t)r0 * asr + lkc;
    const float* a1p = A + (size_t)r1 * asr + lkc;
    const float* b0p = Wslab + (size_t)lrow * K + lkc;
    const float* b1p = Wslab + (size_t)(lrow + 64) * K + lkc;

    const uint32_t sA  = (uint32_t)__cvta_generic_to_shared(As) + (uint32_t)((lrow * ASTRIDE + lkc) * 4);
    const uint32_t sA2 = sA + 64 * ASTRIDE * 4;
    const uint32_t sB  = (uint32_t)__cvta_generic_to_shared(Bs) + (uint32_t)((lrow * ASTRIDE + lkc) * 4);
    const uint32_t sB2 = sB + 64 * ASTRIDE * 4;

    const int KT = K >> 4;
    auto issue = [&](int kt) {
        const int koff = kt * 16;
        const uint32_t so = (uint32_t)((kt & 3) * STAGE_ELEMS * 4);
        cp16(sA  + so, a0p + koff);
        cp16(sA2 + so, a1p + koff);
        cp16(sB  + so, b0p + koff);
        cp16(sB2 + so, b1p + koff);
        cp_commit();
    };

    const int pre = KT < 3 ? KT : 3;
    for (int s = 0; s < pre; ++s) issue(s);

    for (int kt = 0; kt < KT; ++kt) {
        if (kt < KT - 2)       asm volatile("cp.async.wait_group 2;");
        else if (kt == KT - 2) asm volatile("cp.async.wait_group 1;");
        else                   asm volatile("cp.async.wait_group 0;");
        __syncthreads();
        if (kt + 3 < KT) issue(kt + 3);

        const float* Ab = As + (kt & 3) * STAGE_ELEMS;
        const float* Bb = Bs + (kt & 3) * STAGE_ELEMS;
#pragma unroll
        for (int kk = 0; kk < 16; kk += 8) {
            uint32_t af[4][4], bfr[4][2];
#pragma unroll
            for (int mt = 0; mt < 4; mt++) {
                const int r = wm * 64 + mt * 16 + (lane >> 2);
                const int c = kk + (lane & 3);
                af[mt][0] = fbits(Ab[r * ASTRIDE + c]);
                af[mt][1] = fbits(Ab[(r + 8) * ASTRIDE + c]);
                af[mt][2] = fbits(Ab[r * ASTRIDE + c + 4]);
                af[mt][3] = fbits(Ab[(r + 8) * ASTRIDE + c + 4]);
            }
#pragma unroll
            for (int nt = 0; nt < 4; nt++) {
                const int n = wn * 32 + nt * 8 + (lane >> 2);
                bfr[nt][0] = fbits(Bb[n * ASTRIDE + kk + (lane & 3)]);
                bfr[nt][1] = fbits(Bb[n * ASTRIDE + kk + (lane & 3) + 4]);
            }
#pragma unroll
            for (int mt = 0; mt < 4; mt++)
#pragma unroll
                for (int nt = 0; nt < 4; nt++)
                    mma_tf32(acc[mt][nt], af[mt][0], af[mt][1], af[mt][2], af[mt][3],
                             bfr[nt][0], bfr[nt][1]);
        }
    }
    __syncthreads();
}

__launch_bounds__(256, 1)
__global__ void lstm1_kernel(const float* __restrict__ A, long long asr,
                             const float* __restrict__ W,
                             const float* __restrict__ bih, const float* __restrict__ bhh,
                             float* __restrict__ Hout, int M, int K)
{
    extern __shared__ float sm[];
    float* As = sm;
    float* Bs = sm + 4 * STAGE_ELEMS;

    const int tid = threadIdx.x, lane = tid & 31, warp = tid >> 5;
    const int wm = warp >> 2, wn = warp & 3;
    const int mb = blockIdx.y * 128, nb = blockIdx.x * 128;

    float keep[4][4][4];
    const int gset[3] = {0, 2, 3};

#pragma unroll 1
    for (int ph = 0; ph < 3; ++ph) {
        const int g = gset[ph];
        float acc[4][4][4];
#pragma unroll
        for (int a = 0; a < 4; a++)
#pragma unroll
            for (int b = 0; b < 4; b++)
#pragma unroll
                for (int c = 0; c < 4; c++) acc[a][b][c] = 0.0f;

        run_gemm_acc(A, asr, M, mb, W + ((size_t)(g * HH + nb)) * K, K, As, Bs, acc);

#pragma unroll
        for (int mt = 0; mt < 4; mt++) {
#pragma unroll
            for (int nt = 0; nt < 4; nt++) {
                const int gcol = g * HH + nb + wn * 32 + nt * 8 + 2 * (lane & 3);
                const float b0 = bih[gcol] + bhh[gcol];
                const float b1 = bih[gcol + 1] + bhh[gcol + 1];
                if (ph == 0) {
                    keep[mt][nt][0] = sigf(acc[mt][nt][0] + b0);
                    keep[mt][nt][1] = sigf(acc[mt][nt][1] + b1);
                    keep[mt][nt][2] = sigf(acc[mt][nt][2] + b0);
                    keep[mt][nt][3] = sigf(acc[mt][nt][3] + b1);
                } else if (ph == 1) {
                    keep[mt][nt][0] *= tanhf(acc[mt][nt][0] + b0);
                    keep[mt][nt][1] *= tanhf(acc[mt][nt][1] + b1);
                    keep[mt][nt][2] *= tanhf(acc[mt][nt][2] + b0);
                    keep[mt][nt][3] *= tanhf(acc[mt][nt][3] + b1);
                } else {
                    const int row0 = mb + wm * 64 + mt * 16 + (lane >> 2);
                    const int colh = nb + wn * 32 + nt * 8 + 2 * (lane & 3);
                    const float v0 = sigf(acc[mt][nt][0] + b0) * tanhf(keep[mt][nt][0]);
                    const float v1 = sigf(acc[mt][nt][1] + b1) * tanhf(keep[mt][nt][1]);
                    const float v2 = sigf(acc[mt][nt][2] + b0) * tanhf(keep[mt][nt][2]);
                    const float v3 = sigf(acc[mt][nt][3] + b1) * tanhf(keep[mt][nt][3]);
                    *(float2*)(Hout + (size_t)row0 * HH + colh)       = make_float2(v0, v1);
                    *(float2*)(Hout + (size_t)(row0 + 8) * HH + colh) = make_float2(v2, v3);
                }
            }
        }
    }
}

// ------------------------- grid barrier --------------------------------------
__device__ __forceinline__ void grid_bar()
{
    __threadfence();
    __syncthreads();
    if (threadIdx.x == 0) {
        const unsigned gen = g_sense;
        const unsigned arrived = atomicAdd((unsigned*)&g_cnt, 1u);
        if (arrived == NBLK_REC - 1u) {
            g_cnt = 0;
            __threadfence();
            atomicAdd((unsigned*)&g_sense, 1u);
        } else {
            while (g_sense == gen) { __nanosleep(32); }
        }
        __threadfence();
    }
    __syncthreads();
}

// =============================================================================
// RECURRENT LSTM LAYER — TMA bulk-copy edition
//
// 128 CTAs x 256 thr. CTA owns 8 hidden cols (32 gate rows). Whh slab (tf32)
// persists in SMEM. Per step, h arrives via cp.async.bulk from a transposed,
// XOR-swizzled global buffer hT[k][r ^ 8*(k&3)] in 8 chunks of K=128 (32 KB),
// double-buffered, mbarrier-completed. mma: 8-way K-split across warps, each
// warp computes the full 64x32 tile over its K range; fp32 partials reduced
// in SMEM. c state in registers. One grid barrier per step.
// =============================================================================
__launch_bounds__(256, 1)
__global__ void recur_kernel(const float* __restrict__ xg,    // [BT, 4096]
                             const float* __restrict__ Whh,   // [4096, 1024]
                             float* __restrict__ hs,          // [BT, 1024]
                             float* __restrict__ hbufT,       // [2][1024][64] swizzled
                             int write_all)
{
    extern __shared__ float sm[];
    float* Ws   = sm;                     // [32][1028]
    float* tbuf = sm + RW_FLOATS;         // 2 x 8192 floats (h chunks)
    float* part = tbuf;                   // overlay: 8 x [64][34] partials

    const uint32_t smb = (uint32_t)__cvta_generic_to_shared(sm);
    const uint32_t tb_sh = smb + RW_FLOATS * 4;
    const uint32_t mb0 = smb + R_MBAR_F * 4;
    const uint32_t mb1 = mb0 + 8;

    const int tid = threadIdx.x, lane = tid & 31;
    const int wk = tid >> 5;              // warp = K-split index 0..7
    const int p = lane >> 2, q = lane & 3;
    const int n0 = blockIdx.x * 8;

    if (tid == 0) { mbar_init(mb0, 1); mbar_init(mb1, 1); }

    // Whh slab: packed row c = g*8 + j  ->  Whh[g*HH + n0 + j], tf32-rounded
#pragma unroll 1
    for (int c = 0; c < 32; c++) {
        const int g = c >> 3, j = c & 7;
        const float4 v = *(const float4*)(Whh + ((size_t)(g * HH + n0 + j)) * HH + tid * 4);
        float* d = Ws + c * 1028 + tid * 4;
        d[0] = tf32r(v.x); d[1] = tf32r(v.y); d[2] = tf32r(v.z); d[3] = tf32r(v.w);
    }
    __syncthreads();

    // per-thread constant A row positions: (mt*16 + 8h + p) ^ (8q)
    int rowx[4][2];
#pragma unroll
    for (int mt = 0; mt < 4; mt++) {
        rowx[mt][0] = (mt * 16 + p) ^ (8 * q);
        rowx[mt][1] = (mt * 16 + 8 + p) ^ (8 * q);
    }
    // B base pointers per ntile (add ch*128 per chunk)
    const float* wsn[4];
#pragma unroll
    for (int nt = 0; nt < 4; nt++)
        wsn[nt] = Ws + (nt * 8 + p) * 1028 + wk * 16 + q;

    const int tA_off = (wk * 16 + q) * 64;   // within chunk buf

    // elementwise mapping
    const int er0 = tid >> 3, ej = tid & 7, er1 = 32 + (tid >> 3);
    const int hswz0 = er0 ^ (8 * (ej & 3));
    const int hswz1 = er1 ^ (8 * (ej & 3));
    float c0 = 0.f, c1 = 0.f;

    for (int t = 0; t < TT; t++) {
        // issue chunk 0 of this step's h broadcast
        if (t > 0 && tid == 0) {
            const float* src = hbufT + (size_t)(t & 1) * (HH * BB);
            mbar_expect(mb0, 32768);
            bulk_g2s(tb_sh, src, 32768, mb0);
        }

        // prefetch xg (DRAM; consumed at step end)
        const size_t x0 = ((size_t)(er0 * TT + t)) * G4 + n0 + ej;
        const size_t x1 = ((size_t)(er1 * TT + t)) * G4 + n0 + ej;
        const float xi0 = xg[x0], xf0 = xg[x0 + 1024], xgg0 = xg[x0 + 2048], xo0 = xg[x0 + 3072];
        const float xi1 = xg[x1], xf1 = xg[x1 + 1024], xgg1 = xg[x1 + 2048], xo1 = xg[x1 + 3072];

        if (t > 0) {
            const float* src = hbufT + (size_t)(t & 1) * (HH * BB);
            float acc[4][4][4];
#pragma unroll
            for (int a = 0; a < 4; a++)
#pragma unroll
                for (int b = 0; b < 4; b++)
#pragma unroll
                    for (int cc = 0; cc < 4; cc++) acc[a][b][cc] = 0.0f;

            const unsigned rbase = (unsigned)(t - 1) * 4u;

#pragma unroll 1
            for (int ch = 0; ch < 8; ++ch) {
                if (tid == 0 && ch < 7) {
                    const uint32_t m = ((ch + 1) & 1) ? mb1 : mb0;
                    mbar_expect(m, 32768);
                    bulk_g2s(tb_sh + ((ch + 1) & 1) * 32768u, src + (ch + 1) * RT_BUF, 32768, m);
                }
                mbar_wait((ch & 1) ? mb1 : mb0, (rbase + (ch >> 1)) & 1u);

                const float* tA = tbuf + (ch & 1) * RT_BUF + tA_off;
#pragma unroll
                for (int ks = 0; ks < 2; ++ks) {
                    uint32_t a[4][4];
#pragma unroll
                    for (int mt = 0; mt < 4; mt++) {
                        a[mt][0] = fbits(tA[ks * 512 + rowx[mt][0]]);
                        a[mt][1] = fbits(tA[ks * 512 + rowx[mt][1]]);
                        a[mt][2] = fbits(tA[ks * 512 + 256 + rowx[mt][0]]);
                        a[mt][3] = fbits(tA[ks * 512 + 256 + rowx[mt][1]]);
                    }
                    uint32_t bfr[4][2];
#pragma unroll
                    for (int nt = 0; nt < 4; nt++) {
                        bfr[nt][0] = fbits(wsn[nt][ch * 128 + ks * 8]);
                        bfr[nt][1] = fbits(wsn[nt][ch * 128 + ks * 8 + 4]);
                    }
#pragma unroll
                    for (int mt = 0; mt < 4; mt++)
#pragma unroll
                        for (int nt = 0; nt < 4; nt++)
                            mma_tf32(acc[mt][nt], a[mt][0], a[mt][1], a[mt][2], a[mt][3],
                                     bfr[nt][0], bfr[nt][1]);
                }
                __syncthreads();
            }

            // write per-warp partials (overlay on tbuf; all chunk reads done)
            float* pw = part + wk * RP_SZ;
#pragma unroll
            for (int mt = 0; mt < 4; mt++) {
#pragma unroll
                for (int nt = 0; nt < 4; nt++) {
                    const int r = mt * 16 + p;
                    const int cc = nt * 8 + 2 * q;
                    *(float2*)(pw + r * RP_STR + cc)       = make_float2(acc[mt][nt][0], acc[mt][nt][1]);
                    *(float2*)(pw + (r + 8) * RP_STR + cc) = make_float2(acc[mt][nt][2], acc[mt][nt][3]);
                }
            }
            __syncthreads();
        }

        // reduce partials + gate combine + state update
        float gi0 = xi0, gf0 = xf0, gg0 = xgg0, go0 = xo0;
        float gi1 = xi1, gf1 = xf1, gg1 = xgg1, go1 = xo1;
        if (t > 0) {
#pragma unroll
            for (int w = 0; w < 8; w++) {
                const float* pw = part + w * RP_SZ;
                gi0 += pw[er0 * RP_STR + ej];      gf0 += pw[er0 * RP_STR + 8 + ej];
                gg0 += pw[er0 * RP_STR + 16 + ej]; go0 += pw[er0 * RP_STR + 24 + ej];
                gi1 += pw[er1 * RP_STR + ej];      gf1 += pw[er1 * RP_STR + 8 + ej];
                gg1 += pw[er1 * RP_STR + 16 + ej]; go1 += pw[er1 * RP_STR + 24 + ej];
            }
        }
        c0 = sigf(gf0) * c0 + sigf(gi0) * tanhf(gg0);
        c1 = sigf(gf1) * c1 + sigf(gi1) * tanhf(gg1);
        const float h0v = sigf(go0) * tanhf(c0);
        const float h1v = sigf(go1) * tanhf(c1);

        // store h transposed + XOR-swizzled for next step's bulk copy
        float* hT = hbufT + (size_t)((t + 1) & 1) * (HH * BB) + (size_t)(n0 + ej) * BB;
        hT[hswz0] = h0v;
        hT[hswz1] = h1v;
        if (write_all || t == TT - 1) {
            hs[((size_t)(er0 * TT + t)) * HH + n0 + ej] = h0v;
            hs[((size_t)(er1 * TT + t)) * HH + n0 + ej] = h1v;
        }

        if (t < TT - 1) grid_bar();
    }
}

// ------------------------- final MLP layer 3 ---------------------------------
__global__ void mlp3_kernel(const float* __restrict__ z2, const float* __restrict__ W3,
                            const float* __restrict__ b3, float* __restrict__ out)
{
    __shared__ float red[8];
    const int b = blockIdx.x;
    float s = 0.f;
    for (int k = threadIdx.x; k < 512; k += 256) s += z2[b * 512 + k] * W3[k];
#pragma unroll
    for (int o = 16; o; o >>= 1) s += __shfl_down_sync(0xffffffffu, s, o);
    if ((threadIdx.x & 31) == 0) red[threadIdx.x >> 5] = s;
    __syncthreads();
    if (threadIdx.x < 8) {
        s = red[threadIdx.x];
#pragma unroll
        for (int o = 4; o; o >>= 1) s += __shfl_down_sync(0xffu, s, o);
        if (threadIdx.x == 0) out[b] = s + b3[0];
    }
}

// ------------------------- launcher ------------------------------------------
extern "C" void kernel_launch(void* const* d_in, const int* in_sizes, int n_in,
                              void* d_out, int out_size)
{
    const float* xx       = (const float*)d_in[0];
    const float* l1_Wih0  = (const float*)d_in[1];
    const float* l1_bih0  = (const float*)d_in[2];
    const float* l1_bhh0  = (const float*)d_in[3];
    const float* l1_Wih1  = (const float*)d_in[4];
    const float* l1_bih1  = (const float*)d_in[5];
    const float* l1_bhh1  = (const float*)d_in[6];
    const float* l2_Wih0  = (const float*)d_in[7];
    const float* l2_Whh0  = (const float*)d_in[8];
    const float* l2_bih0  = (const float*)d_in[9];
    const float* l2_bhh0  = (const float*)d_in[10];
    const float* l2_Wih1  = (const float*)d_in[11];
    const float* l2_Whh1  = (const float*)d_in[12];
    const float* l2_bih1  = (const float*)d_in[13];
    const float* l2_bhh1  = (const float*)d_in[14];
    const float* mlp_W1   = (const float*)d_in[15];
    const float* mlp_b1   = (const float*)d_in[16];
    const float* mlp_W2   = (const float*)d_in[17];
    const float* mlp_b2   = (const float*)d_in[18];
    const float* mlp_W3   = (const float*)d_in[19];
    const float* mlp_b3   = (const float*)d_in[20];
    float* out = (float*)d_out;

    void* p;
    cudaGetSymbolAddress(&p, g_gates); float* gates = (float*)p;
    cudaGetSymbolAddress(&p, g_h1);    float* h1    = (float*)p;
    cudaGetSymbolAddress(&p, g_h2);    float* h2    = (float*)p;
    cudaGetSymbolAddress(&p, g_hbufT); float* hbufT = (float*)p;
    cudaGetSymbolAddress(&p, g_z1);    float* z1    = (float*)p;
    cudaGetSymbolAddress(&p, g_z2);    float* z2    = (float*)p;

    const int lstm1_smem = 8 * STAGE_ELEMS * 4;
    const int gemm_smem  = 3 * G_ST * 4;
    const int recur_smem = R_SMEM_B;   // 201280
    cudaFuncSetAttribute(gemm_kernel<0>, cudaFuncAttributeMaxDynamicSharedMemorySize, gemm_smem);
    cudaFuncSetAttribute(gemm_kernel<1>, cudaFuncAttributeMaxDynamicSharedMemorySize, gemm_smem);
    cudaFuncSetAttribute(lstm1_kernel,   cudaFuncAttributeMaxDynamicSharedMemorySize, lstm1_smem);
    cudaFuncSetAttribute(recur_kernel,   cudaFuncAttributeMaxDynamicSharedMemorySize, recur_smem);

    const dim3 blk(256);

    // lstm1 (fused, f gate skipped)
    lstm1_kernel<<<dim3(HH / 128, BT / 128), blk, lstm1_smem>>>(xx, 256, l1_Wih0, l1_bih0, l1_bhh0, h1, BT, 256);
    lstm1_kernel<<<dim3(HH / 128, BT / 128), blk, lstm1_smem>>>(h1, HH, l1_Wih1, l1_bih1, l1_bhh1, h2, BT, HH);

    // lstm2 layer 0
    gemm_kernel<0><<<dim3(G4 / 256, BT / 128), blk, gemm_smem>>>(h2, HH, l2_Wih0, l2_bih0, l2_bhh0, gates, BT, G4, HH);
    recur_kernel<<<NBLK_REC, blk, recur_smem>>>(gates, l2_Whh0, h1, hbufT, 1);

    // lstm2 layer 1 (launch idx 5 = the recur below -> profiled by ncu -s 5)
    gemm_kernel<0><<<dim3(G4 / 256, BT / 128), blk, gemm_smem>>>(h1, HH, l2_Wih1, l2_bih1, l2_bhh1, gates, BT, G4, HH);
    recur_kernel<<<NBLK_REC, blk, recur_smem>>>(gates, l2_Whh1, h2, hbufT, 0);

    // MLP on last timestep
    gemm_kernel<1><<<dim3(HH / 256, 1), blk, gemm_smem>>>(h2 + (size_t)(TT - 1) * HH, (long long)TT * HH,
                                                          mlp_W1, mlp_b1, nullptr, z1, BB, HH, HH);
    gemm_kernel<1><<<dim3((HH / 2) / 256, 1), blk, gemm_smem>>>(z1, HH, mlp_W2, mlp_b2, nullptr,
                                                                z2, BB, HH / 2, HH);
    mlp3_kernel<<<BB, blk>>>(z2, mlp_W3, mlp_b3, out);
}